// round 16
// baseline (speedup 1.0000x reference)
#include <cuda_runtime.h>
#include <cuda_bf16.h>
#include <cstdint>

#define BB 128
#define LL 256
#define HH 1024
#define TT 9
#define EST 12                 // padded emission row stride (floats)

#define NCH 7
#define CHS 37                 // 7*37 = 259 >= 256

#define TILE_ROWS 64
#define EGRID ((BB * LL) / TILE_ROWS)   // 512 blocks (4 per batch)
#define ETPB 128
#define NSLAB 16
#define SLABK 64
#define HSTR 68

// Scratch (no allocations allowed)
__device__ __align__(16) float g_emis[BB * LL * EST];
__device__ float g_llh[BB];
__device__ int   g_ctr;
__device__ int   g_done[BB];   // per-batch tile counters, self-resetting

#define CP16(dst, src) \
    asm volatile("cp.async.cg.shared.global [%0], [%1], 16;" :: "r"(dst), "l"(src))
#define CPC() asm volatile("cp.async.commit_group;" ::: "memory")

#define CVT_TF32(d, s) asm("cvt.rna.tf32.f32 %0, %1;" : "=r"(d) : "f"(s))

#define MMA_TF32(d, a0, a1, a2, a3, b0, b1) \
    asm volatile("mma.sync.aligned.m16n8k8.row.col.f32.tf32.tf32.f32 " \
                 "{%0,%1,%2,%3}, {%4,%5,%6,%7}, {%8,%9}, {%0,%1,%2,%3};" \
                 : "+f"(d[0]), "+f"(d[1]), "+f"(d[2]), "+f"(d[3]) \
                 : "r"(a0), "r"(a1), "r"(a2), "r"(a3), "r"(b0), "r"(b1))

// ---------------------------------------------------------------------------
// Fused kernel: tf32-mma emissions (64-row tile per block, cp.async double
// buffer) + per-batch inline CRF run by the 4th finishing tile block.
// ---------------------------------------------------------------------------
__global__ __launch_bounds__(ETPB) void fused_kernel(
    const float* __restrict__ hidden,
    const float* __restrict__ W,
    const float* __restrict__ bias,
    const float* __restrict__ start_t,
    const float* __restrict__ end_t,
    const float* __restrict__ trans,
    const int*   __restrict__ labels,
    const int*   __restrict__ lengths,
    float* __restrict__ out)
{
    extern __shared__ __align__(16) float sm[];
    float* hbuf = sm;                          // [2][64][68]
    float* wbuf = sm + 2 * TILE_ROWS * HSTR;   // [2][16][68]
    __shared__ int trig;

    int tid = threadIdx.x;
    int lane = tid & 31;
    int w = tid >> 5;

    // ================= EMISSIONS (measured-good R15 path) =================
    for (int i = tid; i < 2 * 16 * HSTR; i += ETPB) wbuf[i] = 0.0f;
    __syncthreads();

    uint32_t hB = (uint32_t)__cvta_generic_to_shared(hbuf);
    uint32_t wB = (uint32_t)__cvta_generic_to_shared(wbuf);
    size_t row0 = (size_t)blockIdx.x * TILE_ROWS;

    auto issue = [&](int s) {
        int buf = s & 1;
        uint32_t hd = hB + buf * (TILE_ROWS * HSTR * 4);
        const char* hsrc = (const char*)(hidden + row0 * HH + s * SLABK);
#pragma unroll
        for (int q = 0; q < 8; q++) {
            int g = tid + q * ETPB;
            int r = g >> 4, un = g & 15;
            CP16(hd + (r * HSTR + un * 4) * 4, hsrc + (size_t)r * HH * 4 + un * 16);
        }
#pragma unroll
        for (int q = 0; q < 2; q++) {
            int g = tid + q * ETPB;
            if (g < 144) {
                int r = g >> 4, un = g & 15;
                CP16(wB + buf * (16 * HSTR * 4) + (r * HSTR + un * 4) * 4,
                     (const char*)(W + r * HH + s * SLABK) + un * 16);
            }
        }
        CPC();
    };

    issue(0);

    float d0[4] = {0, 0, 0, 0};
    float d1[4] = {0, 0, 0, 0};
    int ar = lane >> 2;
    int ac = lane & 3;

    for (int s = 0; s < NSLAB; s++) {
        if (s + 1 < NSLAB) {
            issue(s + 1);
            asm volatile("cp.async.wait_group 1;" ::: "memory");
        } else {
            asm volatile("cp.async.wait_group 0;" ::: "memory");
        }
        __syncthreads();

        const float* hc = hbuf + (s & 1) * (TILE_ROWS * HSTR);
        const float* wc = wbuf + (s & 1) * (16 * HSTR);
        const float* abase = hc + (w * 16 + ar) * HSTR + ac;
        const float* bbase = wc + ar * HSTR + ac;

#pragma unroll
        for (int q = 0; q < 8; q++) {
            int k0 = q * 8;
            uint32_t a0, a1, a2, a3, b00, b01, b10, b11;
            CVT_TF32(a0, abase[k0]);
            CVT_TF32(a1, abase[8 * HSTR + k0]);
            CVT_TF32(a2, abase[k0 + 4]);
            CVT_TF32(a3, abase[8 * HSTR + k0 + 4]);
            CVT_TF32(b00, bbase[k0]);
            CVT_TF32(b01, bbase[k0 + 4]);
            CVT_TF32(b10, bbase[8 * HSTR + k0]);
            CVT_TF32(b11, bbase[8 * HSTR + k0 + 4]);
            MMA_TF32(d0, a0, a1, a2, a3, b00, b01);
            MMA_TF32(d1, a0, a1, a2, a3, b10, b11);
        }
        __syncthreads();
    }

    {
        float bs0 = __ldg(&bias[ac * 2]);
        float bs1 = __ldg(&bias[ac * 2 + 1]);
        size_t gr = row0 + (size_t)w * 16 + ar;
        float2 v0 = make_float2(d0[0] + bs0, d0[1] + bs1);
        *(float2*)&g_emis[gr * EST + ac * 2] = v0;
        float2 v1 = make_float2(d0[2] + bs0, d0[3] + bs1);
        *(float2*)&g_emis[(gr + 8) * EST + ac * 2] = v1;
        if (ac == 0) {
            float bs8 = __ldg(&bias[8]);
            g_emis[gr * EST + 8] = d1[0] + bs8;
            g_emis[(gr + 8) * EST + 8] = d1[2] + bs8;
        }
    }

    // ================= per-batch trigger =================
    __threadfence();
    __syncthreads();
    int b = blockIdx.x >> 2;     // 4 tiles per batch
    if (tid == 0) {
        int old = atomicAdd(&g_done[b], 1);
        trig = (old == 3);
        if (old == 3) g_done[b] = 0;  // self-reset for graph replay
    }
    __syncthreads();
    if (!trig) return;
    __threadfence();             // acquire: see all tiles' g_emis writes

    // ================= CRF for batch b (128 threads) =================
    // alias drained hbuf region
    float* u_s  = sm;            // 256*12 = 3072
    float* P_s  = sm + 3072;     // 7*81 = 567
    float* tr_s = sm + 3648;     // 81
    float* Et_s = sm + 3729;     // 81
    float* st_s = sm + 3810;     // 9
    float* en_s = sm + 3819;     // 9
    float* nr_s = sm + 3828;     // 4
    int*   lab_s = (int*)(sm + 3840);  // 256 (16B aligned)
    int*   e_s   = (int*)(sm + 4096);  // 63

    const float* emg = g_emis + (size_t)b * LL * EST;

    {
        const float4* src = (const float4*)emg;
        float4* dst = (float4*)u_s;
#pragma unroll
        for (int i = 0; i < 6; i++) {
            float4 v = __ldcg(src + tid + i * ETPB);
            float4 r;
            r.x = __expf(v.x); r.y = __expf(v.y);
            r.z = __expf(v.z); r.w = __expf(v.w);
            dst[tid + i * ETPB] = r;
        }
    }
    if (tid < LL / 4)
        ((int4*)lab_s)[tid] = __ldcg((const int4*)(labels + (size_t)b * LL) + tid);
    if (tid < 81) {
        float tv = trans[tid];
        tr_s[tid] = tv;
        Et_s[tid] = __expf(tv);
    }
    if (tid < TT) { st_s[tid] = start_t[tid]; en_s[tid] = end_t[tid]; }
    int len = lengths[b];
    __syncthreads();

    // numerator partials (em gathered from L2)
    float num_p = 0.0f;
    for (int t = 1 + tid; t < len; t += ETPB) {
        int pv = lab_s[t - 1], cu = lab_s[t];
        num_p += tr_s[pv * TT + cu] + __ldcg(emg + t * EST + cu);
    }
#pragma unroll
    for (int off = 16; off > 0; off >>= 1)
        num_p += __shfl_xor_sync(0xffffffffu, num_p, off);
    if (lane == 0) nr_s[w] = num_p;

    // scan: 63 (chunk,column) tasks x 2 k-half lanes, pair-masked shuffles
    if (tid < 2 * NCH * TT) {
        int task = tid >> 1;
        int g = tid & 1;
        unsigned pmask = 0x3u << (lane & 30);
        int c = task / TT;
        int j = task - c * TT;
        int lo = (c == 0) ? 1 : CHS * c;
        int hi = min(CHS * (c + 1), len);

        float Eh[45];
#pragma unroll
        for (int i = 0; i < TT; i++)
#pragma unroll
            for (int cc = 0; cc < 5; cc++)
                Eh[i * 5 + cc] =
                    (g && cc == 0) ? 0.0f : Et_s[i * TT + 4 * g + cc];

        float P[TT];
#pragma unroll
        for (int k = 0; k < TT; k++) P[k] = (k == j) ? 1.0f : 0.0f;
        int esum = 0;

        for (int t = hi - 1; t >= lo; t--) {
            const float* u = &u_s[t * EST + 4 * g];
            float wv[5];
#pragma unroll
            for (int cc = 0; cc < 5; cc++) wv[cc] = u[cc] * P[4 * g + cc];

            float np[TT];
#pragma unroll
            for (int i = 0; i < TT; i++) {
                float s = Eh[i * 5] * wv[0];
#pragma unroll
                for (int cc = 1; cc < 5; cc++) s += Eh[i * 5 + cc] * wv[cc];
                np[i] = s;
            }
#pragma unroll
            for (int i = 0; i < TT; i++)
                P[i] = np[i] + __shfl_xor_sync(pmask, np[i], 1);

            if (((hi - t) & 3) == 0) {
                int e = (__float_as_int(P[0]) >> 23) & 255;
                float rr = __int_as_float((254 - e) << 23);  // exact 2^(127-e)
                esum += e - 127;
#pragma unroll
                for (int i = 0; i < TT; i++) P[i] *= rr;
            }
        }

        if (g == 0) {
#pragma unroll
            for (int k = 0; k < TT; k++) P_s[c * 81 + k * TT + j] = P[k];
            e_s[c * TT + j] = esum;
        }
    }
    __syncthreads();

    // combine (warp 0, lane-parallel over columns)
    if (w == 0) {
        float v[TT];
        int G = 0;
#pragma unroll
        for (int k = 0; k < TT; k++)
            v[k] = __expf(st_s[k]) * u_s[k];   // exp(st)+exp(em0) product

        int jj = (lane < TT) ? lane : 0;
#pragma unroll
        for (int c = 0; c < NCH; c++) {
            float s = v[0] * P_s[c * 81 + jj];
#pragma unroll
            for (int k = 1; k < TT; k++) s += v[k] * P_s[c * 81 + k * TT + jj];

            float nv[TT];
#pragma unroll
            for (int k = 0; k < TT; k++) nv[k] = __shfl_sync(0xffffffffu, s, k);

            int ec[TT];
#pragma unroll
            for (int k = 0; k < TT; k++) ec[k] = e_s[c * TT + k];

            int Tk[TT], Tmax;
#pragma unroll
            for (int k = 0; k < TT; k++)
                Tk[k] = G + ec[k] + ((__float_as_int(nv[k]) >> 23) & 255);
            Tmax = Tk[0];
#pragma unroll
            for (int k = 1; k < TT; k++) Tmax = max(Tmax, Tk[k]);
            int Gnew = Tmax - 127;
#pragma unroll
            for (int k = 0; k < TT; k++) {
                int d = G + ec[k] - Gnew;
                v[k] = (d < -126) ? 0.0f : nv[k] * __int_as_float((127 + d) << 23);
            }
            G = Gnew;
        }

        float tot = 0.0f;
#pragma unroll
        for (int k = 0; k < TT; k++) tot += v[k] * __expf(en_s[k]);
        float denom = __logf(tot) + (float)G * 0.6931471805599453f;

        float ns = (lane < 4) ? nr_s[lane] : 0.0f;
#pragma unroll
        for (int off = 2; off > 0; off >>= 1)
            ns += __shfl_xor_sync(0xffffffffu, ns, off);
        ns = __shfl_sync(0xffffffffu, ns, 0);
        int tag0 = lab_s[0];
        float num = ns + st_s[tag0] + __ldcg(emg + tag0) + en_s[lab_s[len - 1]];

        if (lane == 0) g_llh[b] = num - denom;

        // fused finalization: last batch computes -mean(llh)
        __threadfence();
        __syncwarp();
        int last = 0;
        if (lane == 0) {
            int old = atomicAdd(&g_ctr, 1);
            last = (old == BB - 1);
        }
        last = __shfl_sync(0xffffffffu, last, 0);
        if (last) {
            __threadfence();
            float vv = 0.0f;
#pragma unroll
            for (int i = 0; i < BB / 32; i++) vv += g_llh[lane + 32 * i];
#pragma unroll
            for (int off = 16; off > 0; off >>= 1)
                vv += __shfl_xor_sync(0xffffffffu, vv, off);
            if (lane == 0) {
                out[0] = -vv * (1.0f / (float)BB);
                g_ctr = 0;  // self-reset for graph replay
            }
        }
    }
}

extern "C" void kernel_launch(void* const* d_in, const int* in_sizes, int n_in,
                              void* d_out, int out_size)
{
    const float* hidden  = (const float*)d_in[0];
    const float* W       = (const float*)d_in[1];
    const float* bias    = (const float*)d_in[2];
    const float* start_t = (const float*)d_in[3];
    const float* end_t   = (const float*)d_in[4];
    const float* trans   = (const float*)d_in[5];
    const int*   labels  = (const int*)d_in[6];
    const int*   lengths = (const int*)d_in[7];
    float* out = (float*)d_out;

    int smem = (2 * TILE_ROWS * HSTR + 2 * 16 * HSTR) * sizeof(float);  // 43.5KB
    cudaFuncSetAttribute(fused_kernel,
                         cudaFuncAttributeMaxDynamicSharedMemorySize, smem);
    fused_kernel<<<EGRID, ETPB, smem>>>(hidden, W, bias, start_t, end_t,
                                        trans, labels, lengths, out);
}

// round 17
// speedup vs baseline: 1.1788x; 1.1788x over previous
#include <cuda_runtime.h>
#include <cuda_bf16.h>
#include <cstdint>

#define BB 128
#define LL 256
#define HH 1024
#define TT 9
#define EST 12                 // padded emission row stride (floats)

#define NCH 12
#define CHS 22                 // 12*22 = 264 >= 256

#define TILE_ROWS 128
#define EGRID ((BB * LL) / TILE_ROWS)   // 256 blocks (2 per batch)
#define ETPB 256
#define NSLAB 16
#define SLABK 64
#define HSTR 68                // padded smem row stride

// Scratch (no allocations allowed)
__device__ __align__(16) float g_emis[BB * LL * EST];
__device__ float g_llh[BB];
__device__ int   g_ctr;
__device__ int   g_done[BB];   // per-batch tile counters, self-resetting

#define CP16(dst, src) \
    asm volatile("cp.async.cg.shared.global [%0], [%1], 16;" :: "r"(dst), "l"(src))
#define CPC() asm volatile("cp.async.commit_group;" ::: "memory")

#define CVT_TF32(d, s) asm("cvt.rna.tf32.f32 %0, %1;" : "=r"(d) : "f"(s))

#define MMA_TF32(d, a0, a1, a2, a3, b0, b1) \
    asm volatile("mma.sync.aligned.m16n8k8.row.col.f32.tf32.tf32.f32 " \
                 "{%0,%1,%2,%3}, {%4,%5,%6,%7}, {%8,%9}, {%0,%1,%2,%3};" \
                 : "+f"(d[0]), "+f"(d[1]), "+f"(d[2]), "+f"(d[3]) \
                 : "r"(a0), "r"(a1), "r"(a2), "r"(a3), "r"(b0), "r"(b1))

// ---------------------------------------------------------------------------
// Fused kernel: R13's measured-good emis (128-row tiles, 256 thr, 29us @60%
// DRAM) + per-batch inline CRF run by the 2nd finishing tile block.
// ---------------------------------------------------------------------------
__global__ __launch_bounds__(ETPB, 2) void fused_kernel(
    const float* __restrict__ hidden,
    const float* __restrict__ W,
    const float* __restrict__ bias,
    const float* __restrict__ start_t,
    const float* __restrict__ end_t,
    const float* __restrict__ trans,
    const int*   __restrict__ labels,
    const int*   __restrict__ lengths,
    float* __restrict__ out)
{
    extern __shared__ __align__(16) float sm[];
    float* hbuf = sm;                          // [2][128][68]
    float* wbuf = sm + 2 * TILE_ROWS * HSTR;   // [2][16][68]
    __shared__ int trig;

    int tid = threadIdx.x;
    int lane = tid & 31;
    int w = tid >> 5;

    // ================= EMISSIONS (R13 verbatim) =================
    for (int i = tid; i < 2 * 16 * HSTR; i += ETPB) wbuf[i] = 0.0f;
    __syncthreads();

    uint32_t hB = (uint32_t)__cvta_generic_to_shared(hbuf);
    uint32_t wB = (uint32_t)__cvta_generic_to_shared(wbuf);
    size_t row0 = (size_t)blockIdx.x * TILE_ROWS;

    auto issue = [&](int s) {
        int buf = s & 1;
        uint32_t hd = hB + buf * (TILE_ROWS * HSTR * 4);
        const char* hsrc = (const char*)(hidden + row0 * HH + s * SLABK);
#pragma unroll
        for (int q = 0; q < 8; q++) {
            int g = tid + q * ETPB;
            int r = g >> 4, un = g & 15;
            CP16(hd + (r * HSTR + un * 4) * 4, hsrc + (size_t)r * HH * 4 + un * 16);
        }
        if (tid < 144) {
            int r = tid >> 4, un = tid & 15;
            CP16(wB + buf * (16 * HSTR * 4) + (r * HSTR + un * 4) * 4,
                 (const char*)(W + r * HH + s * SLABK) + un * 16);
        }
        CPC();
    };

    issue(0);

    float d0[4] = {0, 0, 0, 0};
    float d1[4] = {0, 0, 0, 0};
    int ar = lane >> 2;
    int ac = lane & 3;

    for (int s = 0; s < NSLAB; s++) {
        if (s + 1 < NSLAB) {
            issue(s + 1);
            asm volatile("cp.async.wait_group 1;" ::: "memory");
        } else {
            asm volatile("cp.async.wait_group 0;" ::: "memory");
        }
        __syncthreads();

        const float* hc = hbuf + (s & 1) * (TILE_ROWS * HSTR);
        const float* wc = wbuf + (s & 1) * (16 * HSTR);
        const float* abase = hc + (w * 16 + ar) * HSTR + ac;
        const float* bbase = wc + ar * HSTR + ac;

#pragma unroll
        for (int q = 0; q < 8; q++) {
            int k0 = q * 8;
            uint32_t a0, a1, a2, a3, b00, b01, b10, b11;
            CVT_TF32(a0, abase[k0]);
            CVT_TF32(a1, abase[8 * HSTR + k0]);
            CVT_TF32(a2, abase[k0 + 4]);
            CVT_TF32(a3, abase[8 * HSTR + k0 + 4]);
            CVT_TF32(b00, bbase[k0]);
            CVT_TF32(b01, bbase[k0 + 4]);
            CVT_TF32(b10, bbase[8 * HSTR + k0]);
            CVT_TF32(b11, bbase[8 * HSTR + k0 + 4]);
            MMA_TF32(d0, a0, a1, a2, a3, b00, b01);
            MMA_TF32(d1, a0, a1, a2, a3, b10, b11);
        }
        __syncthreads();
    }

    {
        float bs0 = __ldg(&bias[ac * 2]);
        float bs1 = __ldg(&bias[ac * 2 + 1]);
        size_t gr = row0 + (size_t)w * 16 + ar;
        float2 v0 = make_float2(d0[0] + bs0, d0[1] + bs1);
        *(float2*)&g_emis[gr * EST + ac * 2] = v0;
        float2 v1 = make_float2(d0[2] + bs0, d0[3] + bs1);
        *(float2*)&g_emis[(gr + 8) * EST + ac * 2] = v1;
        if (ac == 0) {
            float bs8 = __ldg(&bias[8]);
            g_emis[gr * EST + 8] = d1[0] + bs8;
            g_emis[(gr + 8) * EST + 8] = d1[2] + bs8;
        }
    }

    // ================= per-batch trigger (2 tiles/batch) =================
    __threadfence();
    __syncthreads();
    int b = blockIdx.x >> 1;
    if (tid == 0) {
        int old = atomicAdd(&g_done[b], 1);
        trig = (old == 1);
        if (old == 1) g_done[b] = 0;  // self-reset for graph replay
    }
    __syncthreads();
    if (!trig) return;
    __threadfence();              // acquire: see peer tile's g_emis writes

    // ================= CRF for batch b (256 threads) =================
    // alias drained smem
    float* u_s  = sm;             // 3072
    float* P_s  = sm + 3072;      // 972
    float* tr_s = sm + 4044;      // 81
    float* Et_s = sm + 4128;      // 81
    float* st_s = sm + 4212;      // 9
    float* en_s = sm + 4224;      // 9
    float* nr_s = sm + 4236;      // 8
    int*   lab_s = (int*)(sm + 4256);  // 256 ints (16B aligned)
    int*   e_s   = (int*)(sm + 4512);  // 108

    const float* emg = g_emis + (size_t)b * LL * EST;

    {
        const float4* src = (const float4*)emg;
        float4* dst = (float4*)u_s;
#pragma unroll
        for (int i = 0; i < 3; i++) {
            float4 v = __ldcg(src + tid + i * ETPB);
            float4 r;
            r.x = __expf(v.x); r.y = __expf(v.y);
            r.z = __expf(v.z); r.w = __expf(v.w);
            dst[tid + i * ETPB] = r;
        }
    }
    if (tid < LL / 4)
        ((int4*)lab_s)[tid] = __ldcg((const int4*)(labels + (size_t)b * LL) + tid);
    if (tid < 81) {
        float tv = trans[tid];
        tr_s[tid] = tv;
        Et_s[tid] = __expf(tv);
    }
    if (tid < TT) { st_s[tid] = start_t[tid]; en_s[tid] = end_t[tid]; }
    int len = lengths[b];
    __syncthreads();

    // numerator partials
    float num_p = 0.0f;
    for (int t = 1 + tid; t < len; t += ETPB) {
        int pv = lab_s[t - 1], cu = lab_s[t];
        num_p += tr_s[pv * TT + cu] + __ldcg(emg + t * EST + cu);
    }
#pragma unroll
    for (int off = 16; off > 0; off >>= 1)
        num_p += __shfl_xor_sync(0xffffffffu, num_p, off);
    if (lane == 0) nr_s[w] = num_p;

    // scan: 108 (chunk,column) tasks x 2 k-half lanes, pair-masked shuffles
    if (tid < 2 * NCH * TT) {
        int task = tid >> 1;
        int g = tid & 1;
        unsigned pmask = 0x3u << (lane & 30);
        int c = task / TT;
        int j = task - c * TT;
        int lo = (c == 0) ? 1 : CHS * c;
        int hi = min(CHS * (c + 1), len);

        float Eh[45];
#pragma unroll
        for (int i = 0; i < TT; i++)
#pragma unroll
            for (int cc = 0; cc < 5; cc++)
                Eh[i * 5 + cc] =
                    (g && cc == 0) ? 0.0f : Et_s[i * TT + 4 * g + cc];

        float P[TT];
#pragma unroll
        for (int k = 0; k < TT; k++) P[k] = (k == j) ? 1.0f : 0.0f;
        int esum = 0;

        for (int t = hi - 1; t >= lo; t--) {
            const float* u = &u_s[t * EST + 4 * g];
            float wv[5];
#pragma unroll
            for (int cc = 0; cc < 5; cc++) wv[cc] = u[cc] * P[4 * g + cc];

            float np[TT];
#pragma unroll
            for (int i = 0; i < TT; i++) {
                float s = Eh[i * 5] * wv[0];
#pragma unroll
                for (int cc = 1; cc < 5; cc++) s += Eh[i * 5 + cc] * wv[cc];
                np[i] = s;
            }
#pragma unroll
            for (int i = 0; i < TT; i++)
                P[i] = np[i] + __shfl_xor_sync(pmask, np[i], 1);

            if (((hi - t) & 3) == 0) {
                int e = (__float_as_int(P[0]) >> 23) & 255;
                float rr = __int_as_float((254 - e) << 23);  // exact 2^(127-e)
                esum += e - 127;
#pragma unroll
                for (int i = 0; i < TT; i++) P[i] *= rr;
            }
        }

        if (g == 0) {
#pragma unroll
            for (int k = 0; k < TT; k++) P_s[c * 81 + k * TT + j] = P[k];
            e_s[c * TT + j] = esum;
        }
    }
    __syncthreads();

    // combine (warp 0, lane-parallel over columns)
    if (w == 0) {
        float v[TT];
        int G = 0;
#pragma unroll
        for (int k = 0; k < TT; k++)
            v[k] = __expf(st_s[k]) * u_s[k];  // exp(st_k + em0_k)

        int jj = (lane < TT) ? lane : 0;
#pragma unroll
        for (int c = 0; c < NCH; c++) {
            float s = v[0] * P_s[c * 81 + jj];
#pragma unroll
            for (int k = 1; k < TT; k++) s += v[k] * P_s[c * 81 + k * TT + jj];

            float nv[TT];
#pragma unroll
            for (int k = 0; k < TT; k++) nv[k] = __shfl_sync(0xffffffffu, s, k);

            int ec[TT];
#pragma unroll
            for (int k = 0; k < TT; k++) ec[k] = e_s[c * TT + k];

            int Tk[TT], Tmax;
#pragma unroll
            for (int k = 0; k < TT; k++)
                Tk[k] = G + ec[k] + ((__float_as_int(nv[k]) >> 23) & 255);
            Tmax = Tk[0];
#pragma unroll
            for (int k = 1; k < TT; k++) Tmax = max(Tmax, Tk[k]);
            int Gnew = Tmax - 127;
#pragma unroll
            for (int k = 0; k < TT; k++) {
                int d = G + ec[k] - Gnew;
                v[k] = (d < -126) ? 0.0f : nv[k] * __int_as_float((127 + d) << 23);
            }
            G = Gnew;
        }

        float tot = 0.0f;
#pragma unroll
        for (int k = 0; k < TT; k++) tot += v[k] * __expf(en_s[k]);
        float denom = __logf(tot) + (float)G * 0.6931471805599453f;

        float ns = (lane < 8) ? nr_s[lane] : 0.0f;
#pragma unroll
        for (int off = 4; off > 0; off >>= 1)
            ns += __shfl_xor_sync(0xffffffffu, ns, off);
        ns = __shfl_sync(0xffffffffu, ns, 0);
        int tag0 = lab_s[0];
        float num = ns + st_s[tag0] + __ldcg(emg + tag0) + en_s[lab_s[len - 1]];

        if (lane == 0) g_llh[b] = num - denom;

        // fused finalization: last batch computes -mean(llh)
        __threadfence();
        __syncwarp();
        int last = 0;
        if (lane == 0) {
            int old = atomicAdd(&g_ctr, 1);
            last = (old == BB - 1);
        }
        last = __shfl_sync(0xffffffffu, last, 0);
        if (last) {
            __threadfence();
            float vv = 0.0f;
#pragma unroll
            for (int i = 0; i < BB / 32; i++) vv += g_llh[lane + 32 * i];
#pragma unroll
            for (int off = 16; off > 0; off >>= 1)
                vv += __shfl_xor_sync(0xffffffffu, vv, off);
            if (lane == 0) {
                out[0] = -vv * (1.0f / (float)BB);
                g_ctr = 0;  // self-reset for graph replay
            }
        }
    }
}

extern "C" void kernel_launch(void* const* d_in, const int* in_sizes, int n_in,
                              void* d_out, int out_size)
{
    const float* hidden  = (const float*)d_in[0];
    const float* W       = (const float*)d_in[1];
    const float* bias    = (const float*)d_in[2];
    const float* start_t = (const float*)d_in[3];
    const float* end_t   = (const float*)d_in[4];
    const float* trans   = (const float*)d_in[5];
    const int*   labels  = (const int*)d_in[6];
    const int*   lengths = (const int*)d_in[7];
    float* out = (float*)d_out;

    int smem = (2 * TILE_ROWS * HSTR + 2 * 16 * HSTR) * sizeof(float);  // 78336
    cudaFuncSetAttribute(fused_kernel,
                         cudaFuncAttributeMaxDynamicSharedMemorySize, smem);
    fused_kernel<<<EGRID, ETPB, smem>>>(hidden, W, bias, start_t, end_t,
                                        trans, labels, lengths, out);
}